// round 5
// baseline (speedup 1.0000x reference)
#include <cuda_runtime.h>

typedef unsigned long long u64;

#define NBAT 2
#define SQ 400
#define IW 80
#define HD 128
#define FD 256
#define NP 401
#define NPAD 416
#define KPD 128

__device__ float g_xWi[4 * SQ * 512];
__device__ float g_xp [NBAT * NP * FD];
__device__ float g_cum[NBAT * NPAD * FD];
__device__ float g_pxd[NBAT * NP * KPD];
__device__ float g_pxe[NBAT * NP * KPD];
__device__ float g_W1T[FD * KPD];
__device__ ulonglong2 g_WhT[2 * 8 * 256];

__device__ __forceinline__ float preluf(float x, float a) { return x >= 0.f ? x : a * x; }
__device__ __forceinline__ float sigf(float x) { return 1.f / (1.f + __expf(-x)); }
__device__ __forceinline__ void ffma2(u64& c, u64 a, u64 b) {
    asm("fma.rn.f32x2 %0, %1, %2, %0;" : "+l"(c) : "l"(a), "l"(b));
}
__device__ __forceinline__ u64 dupf(float x) {
    u64 r; asm("mov.b64 %0, {%1, %1};" : "=l"(r) : "f"(x)); return r;
}
__device__ __forceinline__ float2 unpk(u64 u) {
    float2 r; asm("mov.b64 {%0, %1}, %2;" : "=f"(r.x), "=f"(r.y) : "l"(u)); return r;
}

// ---- transpose helpers (one-time) ----
__global__ void k_prep(const float* __restrict__ Whf, const float* __restrict__ Whb) {
    const float* Wh = blockIdx.x ? Whb : Whf;
    int r = threadIdx.x;
    const ulonglong2* src = (const ulonglong2*)(Wh + (256 + r) * HD + 96);
#pragma unroll
    for (int q = 0; q < 8; q++) g_WhT[(blockIdx.x * 8 + q) * 256 + r] = src[q];
}
__global__ void k_w1t(const float* __restrict__ W1) {
    int idx = blockIdx.x * 256 + threadIdx.x;         // 32768 total
    int f = idx >> 7, k = idx & 127;
    g_W1T[idx] = (k < 100) ? W1[k * 768 + f] : 0.f;
}

// ---- xWi = x @ Wi^T + b ----
__global__ void k_xwi(const float* __restrict__ x, const float* __restrict__ Wif,
                      const float* __restrict__ bf, const float* __restrict__ Wib,
                      const float* __restrict__ bbv) {
    int t = blockIdx.x, ch = blockIdx.y, d = ch >> 1, bb = ch & 1;
    const float* Wi = d ? Wib : Wif;
    const float* bi = d ? bbv : bf;
    __shared__ __align__(16) float sx[IW];
    int g = threadIdx.x;
    if (g < IW) sx[g] = x[(bb * SQ + t) * IW + g];
    __syncthreads();
    float acc = bi[g];
    const float4* wr = (const float4*)(Wi + g * IW);
    const float4* xr = (const float4*)sx;
#pragma unroll
    for (int q = 0; q < IW / 4; q++) {
        float4 w = wr[q], xv = xr[q];
        acc += w.x * xv.x + w.y * xv.y + w.z * xv.z + w.w * xv.w;
    }
    g_xWi[(ch * SQ + t) * 512 + g] = acc;
}

// ---- LSTM: 4 chains, weights mostly register-resident ----
__global__ void __launch_bounds__(256, 1) k_lstm(const float* __restrict__ Whf,
                                                 const float* __restrict__ Whb) {
    int d = blockIdx.x >> 1, b = blockIdx.x & 1;
    const float* Wh = d ? Whb : Whf;
    int t = threadIdx.x;
    __shared__ ulonglong2 sWs[8][256];
    __shared__ __align__(16) float sh[HD];
    __shared__ float sf[HD], so[HD];
    u64 w1[64], w2[32];
    {
        const ulonglong2* a = (const ulonglong2*)(Wh + t * HD);
#pragma unroll
        for (int q = 0; q < 32; q++) { ulonglong2 v = a[q]; w1[2*q] = v.x; w1[2*q+1] = v.y; }
        const ulonglong2* c0 = (const ulonglong2*)(Wh + (256 + t) * HD);
#pragma unroll
        for (int q = 0; q < 16; q++) { ulonglong2 v = c0[q]; w2[2*q] = v.x; w2[2*q+1] = v.y; }
        const ulonglong2* c1 = (const ulonglong2*)(Wh + (256 + t) * HD + 64);
#pragma unroll
        for (int q = 0; q < 8; q++) sWs[q][t] = c1[q];
    }
    if (t < HD) sh[t] = 0.f;
    float cst = 0.f;
    __syncthreads();
    const ulonglong2* sh2 = (const ulonglong2*)sh;
    const float* xw = g_xWi + (blockIdx.x * SQ) * 512;
    const ulonglong2* gT = &g_WhT[d * 8 * 256];
    float* xpo = g_xp + (b * NP) * FD + d * HD;
    for (int s = 0; s < SQ; s++) {
        int tt = d ? (SQ - 1 - s) : s;
        u64 aA0 = 0, aA1 = 0, aB0 = 0, aB1 = 0;
#pragma unroll
        for (int q = 0; q < 32; q++) {
            ulonglong2 hv = sh2[q];
            ffma2(aA0, hv.x, w1[2*q]); ffma2(aA1, hv.y, w1[2*q+1]);
            if (q < 16)      { ffma2(aB0, hv.x, w2[2*q]); ffma2(aB1, hv.y, w2[2*q+1]); }
            else if (q < 24) { ulonglong2 wv = sWs[q-16][t]; ffma2(aB0, hv.x, wv.x); ffma2(aB1, hv.y, wv.y); }
            else             { ulonglong2 wv = gT[(q-24)*256 + t]; ffma2(aB0, hv.x, wv.x); ffma2(aB1, hv.y, wv.y); }
        }
        float2 p0 = unpk(aA0), p1 = unpk(aA1), p2 = unpk(aB0), p3 = unpk(aB1);
        float gA = xw[tt*512 + t]       + (p0.x + p0.y) + (p1.x + p1.y);
        float gB = xw[tt*512 + 256 + t] + (p2.x + p2.y) + (p3.x + p3.y);
        if (t >= HD) { sf[t - HD] = gA; so[t - HD] = gB; }
        __syncthreads();
        if (t < HD) {
            float iv = sigf(gA), fv = sigf(sf[t]);
            float gv = tanhf(gB), ov = sigf(so[t]);
            cst = fv * cst + iv * gv;
            float h = ov * tanhf(cst);
            sh[t] = h;
            xpo[(tt + 1) * FD + t] = h;
        }
        __syncthreads();
    }
}

// ---- cumsum (+ zero pads) ----
__global__ void k_cumsum() {
    int b = threadIdx.x >> 8, f = threadIdx.x & 255;
    float* xp = g_xp + b * NP * FD + f;
    float* cm = g_cum + b * NPAD * FD + f;
    xp[0] = 0.f; cm[0] = 0.f;
    float a = 0.f;
    for (int n = 1; n < NP; n++) { a += xp[n * FD]; cm[n * FD] = a; }
    for (int n = NP; n < NPAD; n++) cm[n * FD] = 0.f;
}

// ---- pxd = prelu(xp)@W1d^T + b1 ; pxe = prelu(xp)@W1e^T (k padded to 128) ----
__global__ void k_pxde(const float* __restrict__ W1, const float* __restrict__ b1,
                       const float* __restrict__ a1) {
    int n = blockIdx.x, b = blockIdx.y, t = threadIdx.x;
    __shared__ __align__(16) float sx[FD];
    float A = a1[0];
    sx[t] = preluf(g_xp[(b * NP + n) * FD + t], A);
    __syncthreads();
    int k = t & 127, which = t >> 7;
    float* dst = (which ? g_pxe : g_pxd) + (b * NP + n) * KPD + k;
    if (k >= 100) { *dst = 0.f; return; }
    const float4* wr = (const float4*)(W1 + k * 768 + (which ? 512 : 256));
    const float4* xr = (const float4*)sx;
    float acc = which ? 0.f : b1[k];
#pragma unroll 16
    for (int q = 0; q < 64; q++) {
        float4 w = wr[q], xv = xr[q];
        acc += w.x * xv.x + w.y * xv.y + w.z * xv.z + w.w * xv.w;
    }
    *dst = acc;
}

// ---- big span-scoring kernel ----
#define OFF_V   32768
#define OFF_CI  (32768 + 64 * 210)
#define OFF_PXD (OFF_CI + 256)
#define OFF_W2  (OFF_PXD + 128)
#define SMEM_FLOATS (OFF_W2 + 128)

__global__ void __launch_bounds__(256, 1)
k_scores(const float* __restrict__ W2, const float* __restrict__ b2,
         const float* __restrict__ a1p, const float* __restrict__ a2p,
         float* __restrict__ outp) {
    extern __shared__ __align__(16) float sm[];
    float* sW  = sm;
    float* sV  = sm + OFF_V;
    float* sCI = sm + OFF_CI;
    float* sPD = sm + OFF_PXD;
    float* sW2 = sm + OFF_W2;
    int i = blockIdx.x, b = blockIdx.y, tid = threadIdx.x;
    int w = tid >> 5, l = tid & 31;
    float A1 = a1p[0], A2 = a2p[0], B2 = b2[0];
    for (int idx = tid; idx < 32768; idx += 256) sW[idx] = g_W1T[idx];
    sCI[tid] = g_cum[(b * NPAD + i) * FD + tid];
    if (tid < 128) {
        sPD[tid] = g_pxd[(b * NP + i) * KPD + tid];
        sW2[tid] = (tid < 100) ? W2[tid] : 0.f;
    }
    for (int pass = 0; pass < 2; pass++) {
        int jbase = pass * 208;
        int j0w = jbase + w * 26;
        u64 acc[13][4];
#pragma unroll
        for (int jp = 0; jp < 13; jp++) { acc[jp][0]=0; acc[jp][1]=0; acc[jp][2]=0; acc[jp][3]=0; }
        for (int fc = 0; fc < 4; fc++) {
            __syncthreads();
            for (int idx = tid; idx < 208 * 64; idx += 256) {
                int jl = idx >> 6, fl = idx & 63;
                int f = fc * 64 + fl;
                sV[fl * 210 + jl] = preluf(g_cum[(b * NPAD + jbase + jl) * FD + f] - sCI[f], A1);
            }
            __syncthreads();
            const float* sWf = sW + (fc * 64) * 128;
            for (int f = 0; f < 64; f++) {
                const u64* vr = (const u64*)(sV + f * 210 + w * 26);
                float4 wv = ((const float4*)(sWf + f * 128))[l];
                u64 d0 = dupf(wv.x), d1 = dupf(wv.y), d2 = dupf(wv.z), d3 = dupf(wv.w);
#pragma unroll
                for (int jp = 0; jp < 13; jp++) {
                    u64 v = vr[jp];
                    ffma2(acc[jp][0], v, d0); ffma2(acc[jp][1], v, d1);
                    ffma2(acc[jp][2], v, d2); ffma2(acc[jp][3], v, d3);
                }
            }
        }
        // epilogue
#pragma unroll
        for (int jp = 0; jp < 13; jp++) {
            float2 u0 = unpk(acc[jp][0]), u1 = unpk(acc[jp][1]);
            float2 u2 = unpk(acc[jp][2]), u3 = unpk(acc[jp][3]);
#pragma unroll
            for (int half = 0; half < 2; half++) {
                int j = j0w + 2 * jp + half;
                float s = 0.f;
                if (j < NP) {
                    float4 pe = *(const float4*)(g_pxe + (b * NP + j) * KPD + 4 * l);
                    float a0 = half ? u0.y : u0.x, a1v = half ? u1.y : u1.x;
                    float a2v = half ? u2.y : u2.x, a3 = half ? u3.y : u3.x;
                    float h0 = a0 + sPD[4*l]   + pe.x;
                    float h1 = a1v + sPD[4*l+1] + pe.y;
                    float h2 = a2v + sPD[4*l+2] + pe.z;
                    float h3 = a3 + sPD[4*l+3] + pe.w;
                    s = preluf(h0,A2)*sW2[4*l] + preluf(h1,A2)*sW2[4*l+1]
                      + preluf(h2,A2)*sW2[4*l+2] + preluf(h3,A2)*sW2[4*l+3];
                }
#pragma unroll
                for (int off = 16; off; off >>= 1) s += __shfl_xor_sync(0xffffffffu, s, off);
                if (j < NP && l == 0) outp[(b * NP + i) * NP + j] = s + B2;
            }
        }
    }
}

// ---- cls / bin heads ----
__global__ void k_heads(const float* __restrict__ Wc1, const float* __restrict__ bc1,
                        const float* __restrict__ Wc2, const float* __restrict__ bc2,
                        const float* __restrict__ Wb1, const float* __restrict__ bb1,
                        const float* __restrict__ Wb2, const float* __restrict__ bb2,
                        const float* __restrict__ ac1, const float* __restrict__ ac2,
                        const float* __restrict__ ab1, const float* __restrict__ ab2,
                        float* __restrict__ oc, float* __restrict__ ob) {
    int t = blockIdx.x, b = blockIdx.y, tid = threadIdx.x;
    __shared__ __align__(16) float prc[FD], prb[FD], hc[100], hb[100];
    float x = g_xp[(b * NP + t + 1) * FD + tid];
    prc[tid] = preluf(x, ac1[0]);
    prb[tid] = preluf(x, ab1[0]);
    __syncthreads();
    if (tid < 100) {
        float acc = bc1[tid];
        const float4* wr = (const float4*)(Wc1 + tid * FD);
        const float4* xr = (const float4*)prc;
#pragma unroll 8
        for (int q = 0; q < 64; q++) {
            float4 wv = wr[q], xv = xr[q];
            acc += wv.x*xv.x + wv.y*xv.y + wv.z*xv.z + wv.w*xv.w;
        }
        hc[tid] = preluf(acc, ac2[0]);
    } else if (tid >= 128 && tid < 228) {
        int k = tid - 128;
        float acc = bb1[k];
        const float4* wr = (const float4*)(Wb1 + k * FD);
        const float4* xr = (const float4*)prb;
#pragma unroll 8
        for (int q = 0; q < 64; q++) {
            float4 wv = wr[q], xv = xr[q];
            acc += wv.x*xv.x + wv.y*xv.y + wv.z*xv.z + wv.w*xv.w;
        }
        hb[k] = preluf(acc, ab2[0]);
    }
    __syncthreads();
    if (tid < 50) {
        float acc = bc2[tid];
        for (int q = 0; q < 100; q++) acc += Wc2[tid * 100 + q] * hc[q];
        oc[(b * SQ + t) * 50 + tid] = acc;
    } else if (tid >= 64 && tid < 66) {
        int r = tid - 64;
        float acc = bb2[r];
        for (int q = 0; q < 100; q++) acc += Wb2[r * 100 + q] * hb[q];
        ob[(b * SQ + t) * 2 + r] = acc;
    }
}

// ---- banded Viterbi DP ----
__global__ void k_dp(const int* __restrict__ lengths, float* __restrict__ outp) {
    int b = threadIdx.x >> 5, l = threadIdx.x & 31;
    __shared__ float best[NBAT][NP];
    for (int n = l; n < NP; n += 32) best[b][n] = 0.f;
    float* prevrow = outp + 363204 + b * NP;
    float* preds   = outp + 363202;
    if (l == 0) prevrow[0] = 0.f;
    __syncwarp();
    for (int i = 1; i < NP; i++) {
        int lo = i - 50; if (lo < 0) lo = 0;
        float v = -1e30f; int kk = 0;
        for (int k = lo + l; k < i; k += 32) {
            float c = best[b][k] + outp[(b * NP + k) * NP + i];
            if (c > v) { v = c; kk = k; }
        }
#pragma unroll
        for (int off = 16; off; off >>= 1) {
            float v2 = __shfl_xor_sync(0xffffffffu, v, off);
            int k2 = __shfl_xor_sync(0xffffffffu, kk, off);
            if (v2 > v || (v2 == v && k2 < kk)) { v = v2; kk = k2; }
        }
        if (l == 0) { best[b][i] = v; prevrow[i] = (float)kk; }
        __syncwarp();
    }
    if (l == 0) preds[b] = best[b][lengths[b]];
}

extern "C" void kernel_launch(void* const* d_in, const int* in_sizes, int n_in,
                              void* d_out, int out_size) {
    const float* x    = (const float*)d_in[0];
    const int*   len  = (const int*)  d_in[1];
    const float* Wif  = (const float*)d_in[2];
    const float* Whf  = (const float*)d_in[3];
    const float* bf   = (const float*)d_in[4];
    const float* Wib  = (const float*)d_in[5];
    const float* Whb  = (const float*)d_in[6];
    const float* bbv  = (const float*)d_in[7];
    const float* a1   = (const float*)d_in[8];
    const float* W1   = (const float*)d_in[9];
    const float* b1   = (const float*)d_in[10];
    const float* a2   = (const float*)d_in[11];
    const float* W2   = (const float*)d_in[12];
    const float* b2   = (const float*)d_in[13];
    const float* ac1  = (const float*)d_in[14];
    const float* Wc1  = (const float*)d_in[15];
    const float* bc1  = (const float*)d_in[16];
    const float* ac2  = (const float*)d_in[17];
    const float* Wc2  = (const float*)d_in[18];
    const float* bc2  = (const float*)d_in[19];
    const float* ab1  = (const float*)d_in[20];
    const float* Wb1  = (const float*)d_in[21];
    const float* bb1  = (const float*)d_in[22];
    const float* ab2  = (const float*)d_in[23];
    const float* Wb2  = (const float*)d_in[24];
    const float* bb2  = (const float*)d_in[25];
    float* out = (float*)d_out;

    static int smem_set = 0;
    if (!smem_set) {
        cudaFuncSetAttribute(k_scores, cudaFuncAttributeMaxDynamicSharedMemorySize,
                             SMEM_FLOATS * 4);
        smem_set = 1;
    }

    k_prep<<<2, 256>>>(Whf, Whb);
    k_w1t<<<128, 256>>>(W1);
    k_xwi<<<dim3(SQ, 4), 512>>>(x, Wif, bf, Wib, bbv);
    k_lstm<<<4, 256>>>(Whf, Whb);
    k_cumsum<<<1, 512>>>();
    k_pxde<<<dim3(NP, NBAT), 256>>>(W1, b1, a1);
    k_heads<<<dim3(SQ, NBAT), 256>>>(Wc1, bc1, Wc2, bc2, Wb1, bb1, Wb2, bb2,
                                     ac1, ac2, ab1, ab2,
                                     out + 321602, out + 361602);
    k_scores<<<dim3(NP, NBAT), 256, SMEM_FLOATS * 4>>>(W2, b2, a1, a2, out);
    k_dp<<<1, 64>>>(len, out);
}

// round 6
// speedup vs baseline: 1.0993x; 1.0993x over previous
#include <cuda_runtime.h>

typedef unsigned long long u64;

#define NBAT 2
#define SQ 400
#define IW 80
#define HD 128
#define FD 256
#define NP 401
#define NPAD 416
#define KPD 128

__device__ float g_xWi[4 * SQ * 512];
__device__ float g_xp [NBAT * NP * FD];
__device__ float g_cum[NBAT * NPAD * FD];
__device__ float g_pxd[NBAT * NP * KPD];
__device__ float g_pxe[NBAT * NP * KPD];
__device__ float g_W1T[FD * KPD];
__device__ float g_sT [NBAT * NP * NP];
__device__ ulonglong2 g_WhT[2 * 10 * 256];

__device__ __forceinline__ float preluf(float x, float a) { return x >= 0.f ? x : a * x; }
__device__ __forceinline__ float sigf(float x) { return 1.f / (1.f + __expf(-x)); }
__device__ __forceinline__ float tanhfast(float x) {
    float xc = fminf(fmaxf(x, -15.f), 15.f);
    float t = __expf(-2.f * xc);
    return (1.f - t) / (1.f + t);
}
__device__ __forceinline__ void ffma2(u64& c, u64 a, u64 b) {
    asm("fma.rn.f32x2 %0, %1, %2, %0;" : "+l"(c) : "l"(a), "l"(b));
}
__device__ __forceinline__ u64 dupf(float x) {
    u64 r; asm("mov.b64 %0, {%1, %1};" : "=l"(r) : "f"(x)); return r;
}
__device__ __forceinline__ float2 unpk(u64 u) {
    float2 r; asm("mov.b64 {%0, %1}, %2;" : "=f"(r.x), "=f"(r.y) : "l"(u)); return r;
}

// ---- transpose helpers (one-time) ----
__global__ void k_prep(const float* __restrict__ Whf, const float* __restrict__ Whb) {
    const float* Wh = blockIdx.x ? Whb : Whf;
    int r = threadIdx.x;
    const ulonglong2* src = (const ulonglong2*)(Wh + (256 + r) * HD + 88);
#pragma unroll
    for (int q = 0; q < 10; q++) g_WhT[(blockIdx.x * 10 + q) * 256 + r] = src[q];
}
__global__ void k_w1t(const float* __restrict__ W1) {
    int idx = blockIdx.x * 256 + threadIdx.x;
    int f = idx >> 7, k = idx & 127;
    g_W1T[idx] = (k < 100) ? W1[k * 768 + f] : 0.f;
}

// ---- xWi = x @ Wi^T + b ----
__global__ void k_xwi(const float* __restrict__ x, const float* __restrict__ Wif,
                      const float* __restrict__ bf, const float* __restrict__ Wib,
                      const float* __restrict__ bbv) {
    int t = blockIdx.x, ch = blockIdx.y, d = ch >> 1, bb = ch & 1;
    const float* Wi = d ? Wib : Wif;
    const float* bi = d ? bbv : bf;
    __shared__ __align__(16) float sx[IW];
    int g = threadIdx.x;
    if (g < IW) sx[g] = x[(bb * SQ + t) * IW + g];
    __syncthreads();
    float acc = bi[g];
    const float4* wr = (const float4*)(Wi + g * IW);
    const float4* xr = (const float4*)sx;
#pragma unroll
    for (int q = 0; q < IW / 4; q++) {
        float4 w = wr[q], xv = xr[q];
        acc += w.x * xv.x + w.y * xv.y + w.z * xv.z + w.w * xv.w;
    }
    g_xWi[(ch * SQ + t) * 512 + g] = acc;
}

// ---- LSTM: 4 chains; 176 weight regs + 40KB smem + 40KB L1-resident stream ----
__global__ void __launch_bounds__(256, 1) k_lstm(const float* __restrict__ Whf,
                                                 const float* __restrict__ Whb) {
    int d = blockIdx.x >> 1, b = blockIdx.x & 1;
    const float* Wh = d ? Whb : Whf;
    int t = threadIdx.x;
    __shared__ ulonglong2 sWs[10][256];          // row 256+t, cols 48..87
    __shared__ __align__(16) float sh[HD];
    __shared__ float sf[HD], so[HD];
    u64 w1[64], w2[24];
    {
        const ulonglong2* a = (const ulonglong2*)(Wh + t * HD);
#pragma unroll
        for (int q = 0; q < 32; q++) { ulonglong2 v = a[q]; w1[2*q] = v.x; w1[2*q+1] = v.y; }
        const ulonglong2* c0 = (const ulonglong2*)(Wh + (256 + t) * HD);
#pragma unroll
        for (int q = 0; q < 12; q++) { ulonglong2 v = c0[q]; w2[2*q] = v.x; w2[2*q+1] = v.y; }
        const ulonglong2* c1 = (const ulonglong2*)(Wh + (256 + t) * HD + 48);
#pragma unroll
        for (int q = 0; q < 10; q++) sWs[q][t] = c1[q];
    }
    if (t < HD) sh[t] = 0.f;
    float cst = 0.f;
    __syncthreads();
    const ulonglong2* sh2 = (const ulonglong2*)sh;
    const float* xw = g_xWi + (blockIdx.x * SQ) * 512;
    const ulonglong2* gT = &g_WhT[d * 10 * 256];
    float* xpo = g_xp + (b * NP) * FD + d * HD;
    for (int s = 0; s < SQ; s++) {
        int tt = d ? (SQ - 1 - s) : s;
        float xwA = xw[tt * 512 + t];
        float xwB = xw[tt * 512 + 256 + t];
        u64 aA0 = 0, aA1 = 0, aB0 = 0, aB1 = 0;
#pragma unroll
        for (int q = 0; q < 32; q++) {
            ulonglong2 hv = sh2[q];
            ffma2(aA0, hv.x, w1[2*q]); ffma2(aA1, hv.y, w1[2*q+1]);
            if (q < 12)      { ffma2(aB0, hv.x, w2[2*q]); ffma2(aB1, hv.y, w2[2*q+1]); }
            else if (q < 22) { ulonglong2 wv = sWs[q-12][t]; ffma2(aB0, hv.x, wv.x); ffma2(aB1, hv.y, wv.y); }
            else             { ulonglong2 wv = gT[(q-22)*256 + t]; ffma2(aB0, hv.x, wv.x); ffma2(aB1, hv.y, wv.y); }
        }
        float2 p0 = unpk(aA0), p1 = unpk(aA1), p2 = unpk(aB0), p3 = unpk(aB1);
        float gA = xwA + (p0.x + p0.y) + (p1.x + p1.y);
        float gB = xwB + (p2.x + p2.y) + (p3.x + p3.y);
        if (t >= HD) { sf[t - HD] = gA; so[t - HD] = gB; }
        __syncthreads();
        if (t < HD) {
            float iv = sigf(gA), fv = sigf(sf[t]);
            float gv = tanhfast(gB), ov = sigf(so[t]);
            cst = fv * cst + iv * gv;
            float h = ov * tanhfast(cst);
            sh[t] = h;
            xpo[(tt + 1) * FD + t] = h;
        }
        __syncthreads();
    }
}

// ---- cumsum (+ zero pads) ----
__global__ void k_cumsum() {
    int b = threadIdx.x >> 8, f = threadIdx.x & 255;
    float* xp = g_xp + b * NP * FD + f;
    float* cm = g_cum + b * NPAD * FD + f;
    xp[0] = 0.f; cm[0] = 0.f;
    float a = 0.f;
    for (int n = 1; n < NP; n++) { a += xp[n * FD]; cm[n * FD] = a; }
    for (int n = NP; n < NPAD; n++) cm[n * FD] = 0.f;
}

// ---- pxd / pxe ----
__global__ void k_pxde(const float* __restrict__ W1, const float* __restrict__ b1,
                       const float* __restrict__ a1) {
    int n = blockIdx.x, b = blockIdx.y, t = threadIdx.x;
    __shared__ __align__(16) float sx[FD];
    float A = a1[0];
    sx[t] = preluf(g_xp[(b * NP + n) * FD + t], A);
    __syncthreads();
    int k = t & 127, which = t >> 7;
    float* dst = (which ? g_pxe : g_pxd) + (b * NP + n) * KPD + k;
    if (k >= 100) { *dst = 0.f; return; }
    const float4* wr = (const float4*)(W1 + k * 768 + (which ? 512 : 256));
    const float4* xr = (const float4*)sx;
    float acc = which ? 0.f : b1[k];
#pragma unroll 16
    for (int q = 0; q < 64; q++) {
        float4 w = wr[q], xv = xr[q];
        acc += w.x * xv.x + w.y * xv.y + w.z * xv.z + w.w * xv.w;
    }
    *dst = acc;
}

// ---- big span-scoring kernel ----
#define OFF_V   32768
#define OFF_CI  (32768 + 64 * 210)
#define OFF_PXD (OFF_CI + 256)
#define OFF_W2  (OFF_PXD + 128)
#define SMEM_FLOATS (OFF_W2 + 128)

__global__ void __launch_bounds__(256, 1)
k_scores(const float* __restrict__ W2, const float* __restrict__ b2,
         const float* __restrict__ a1p, const float* __restrict__ a2p,
         float* __restrict__ outp) {
    extern __shared__ __align__(16) float sm[];
    float* sW  = sm;
    float* sV  = sm + OFF_V;
    float* sCI = sm + OFF_CI;
    float* sPD = sm + OFF_PXD;
    float* sW2 = sm + OFF_W2;
    int i = blockIdx.x, b = blockIdx.y, tid = threadIdx.x;
    int w = tid >> 5, l = tid & 31;
    float A1 = a1p[0], A2 = a2p[0], B2 = b2[0];
    for (int idx = tid; idx < 32768; idx += 256) sW[idx] = g_W1T[idx];
    sCI[tid] = g_cum[(b * NPAD + i) * FD + tid];
    if (tid < 128) {
        sPD[tid] = g_pxd[(b * NP + i) * KPD + tid];
        sW2[tid] = (tid < 100) ? W2[tid] : 0.f;
    }
    for (int pass = 0; pass < 2; pass++) {
        int jbase = pass * 208;
        int j0w = jbase + w * 26;
        u64 acc[13][4];
#pragma unroll
        for (int jp = 0; jp < 13; jp++) { acc[jp][0]=0; acc[jp][1]=0; acc[jp][2]=0; acc[jp][3]=0; }
        for (int fc = 0; fc < 4; fc++) {
            __syncthreads();
            for (int idx = tid; idx < 208 * 64; idx += 256) {
                int jl = idx >> 6, fl = idx & 63;
                int f = fc * 64 + fl;
                sV[fl * 210 + jl] = preluf(g_cum[(b * NPAD + jbase + jl) * FD + f] - sCI[f], A1);
            }
            __syncthreads();
            const float* sWf = sW + (fc * 64) * 128;
            for (int f = 0; f < 64; f++) {
                const u64* vr = (const u64*)(sV + f * 210 + w * 26);
                float4 wv = ((const float4*)(sWf + f * 128))[l];
                u64 d0 = dupf(wv.x), d1 = dupf(wv.y), d2 = dupf(wv.z), d3 = dupf(wv.w);
#pragma unroll
                for (int jp = 0; jp < 13; jp++) {
                    u64 v = vr[jp];
                    ffma2(acc[jp][0], v, d0); ffma2(acc[jp][1], v, d1);
                    ffma2(acc[jp][2], v, d2); ffma2(acc[jp][3], v, d3);
                }
            }
        }
#pragma unroll
        for (int jp = 0; jp < 13; jp++) {
            float2 u0 = unpk(acc[jp][0]), u1 = unpk(acc[jp][1]);
            float2 u2 = unpk(acc[jp][2]), u3 = unpk(acc[jp][3]);
#pragma unroll
            for (int half = 0; half < 2; half++) {
                int j = j0w + 2 * jp + half;
                float s = 0.f;
                if (j < NP) {
                    float4 pe = *(const float4*)(g_pxe + (b * NP + j) * KPD + 4 * l);
                    float a0 = half ? u0.y : u0.x, a1v = half ? u1.y : u1.x;
                    float a2v = half ? u2.y : u2.x, a3 = half ? u3.y : u3.x;
                    float h0 = a0 + sPD[4*l]   + pe.x;
                    float h1 = a1v + sPD[4*l+1] + pe.y;
                    float h2 = a2v + sPD[4*l+2] + pe.z;
                    float h3 = a3 + sPD[4*l+3] + pe.w;
                    s = preluf(h0,A2)*sW2[4*l] + preluf(h1,A2)*sW2[4*l+1]
                      + preluf(h2,A2)*sW2[4*l+2] + preluf(h3,A2)*sW2[4*l+3];
                }
#pragma unroll
                for (int off = 16; off; off >>= 1) s += __shfl_xor_sync(0xffffffffu, s, off);
                if (j < NP && l == 0) {
                    float r = s + B2;
                    outp[(b * NP + i) * NP + j] = r;
                    g_sT[(b * NP + j) * NP + i] = r;
                }
            }
        }
    }
}

// ---- cls / bin heads ----
__global__ void k_heads(const float* __restrict__ Wc1, const float* __restrict__ bc1,
                        const float* __restrict__ Wc2, const float* __restrict__ bc2,
                        const float* __restrict__ Wb1, const float* __restrict__ bb1,
                        const float* __restrict__ Wb2, const float* __restrict__ bb2,
                        const float* __restrict__ ac1, const float* __restrict__ ac2,
                        const float* __restrict__ ab1, const float* __restrict__ ab2,
                        float* __restrict__ oc, float* __restrict__ ob) {
    int t = blockIdx.x, b = blockIdx.y, tid = threadIdx.x;
    __shared__ __align__(16) float prc[FD], prb[FD], hc[100], hb[100];
    float x = g_xp[(b * NP + t + 1) * FD + tid];
    prc[tid] = preluf(x, ac1[0]);
    prb[tid] = preluf(x, ab1[0]);
    __syncthreads();
    if (tid < 100) {
        float acc = bc1[tid];
        const float4* wr = (const float4*)(Wc1 + tid * FD);
        const float4* xr = (const float4*)prc;
#pragma unroll 8
        for (int q = 0; q < 64; q++) {
            float4 wv = wr[q], xv = xr[q];
            acc += wv.x*xv.x + wv.y*xv.y + wv.z*xv.z + wv.w*xv.w;
        }
        hc[tid] = preluf(acc, ac2[0]);
    } else if (tid >= 128 && tid < 228) {
        int k = tid - 128;
        float acc = bb1[k];
        const float4* wr = (const float4*)(Wb1 + k * FD);
        const float4* xr = (const float4*)prb;
#pragma unroll 8
        for (int q = 0; q < 64; q++) {
            float4 wv = wr[q], xv = xr[q];
            acc += wv.x*xv.x + wv.y*xv.y + wv.z*xv.z + wv.w*xv.w;
        }
        hb[k] = preluf(acc, ab2[0]);
    }
    __syncthreads();
    if (tid < 50) {
        float acc = bc2[tid];
        for (int q = 0; q < 100; q++) acc += Wc2[tid * 100 + q] * hc[q];
        oc[(b * SQ + t) * 50 + tid] = acc;
    } else if (tid >= 64 && tid < 66) {
        int r = tid - 64;
        float acc = bb2[r];
        for (int q = 0; q < 100; q++) acc += Wb2[r * 100 + q] * hb[q];
        ob[(b * SQ + t) * 2 + r] = acc;
    }
}

// ---- banded Viterbi DP (transposed reads + 1-deep prefetch) ----
__global__ void k_dp(const int* __restrict__ lengths, float* __restrict__ outp) {
    int b = threadIdx.x >> 5, l = threadIdx.x & 31;
    __shared__ float best[NBAT][NP];
    for (int n = l; n < NP; n += 32) best[b][n] = 0.f;
    float* prevrow = outp + 363204 + b * NP;
    float* preds   = outp + 363202;
    if (l == 0) prevrow[0] = 0.f;
    __syncwarp();
    const float* sT = g_sT + b * NP * NP;
    float p0 = sT[1 * NP + l];
    float p1 = sT[1 * NP + (l + 32 > NP - 1 ? NP - 1 : l + 32)];
    for (int i = 1; i < NP; i++) {
        int k0 = i - 50; if (k0 < 0) k0 = 0;
        int cnt = i - k0;
        float c0 = (l < cnt)      ? best[b][k0 + l]      + p0 : -1e30f;
        float c1 = (l + 32 < cnt) ? best[b][k0 + l + 32] + p1 : -1e30f;
        if (i + 1 < NP) {
            int kn = i + 1 - 50; if (kn < 0) kn = 0;
            int i2 = kn + l + 32; if (i2 > NP - 1) i2 = NP - 1;
            p0 = sT[(i + 1) * NP + kn + l];
            p1 = sT[(i + 1) * NP + i2];
        }
        float v = c0; int kk = k0 + l;
        if (c1 > v) { v = c1; kk = k0 + l + 32; }
#pragma unroll
        for (int off = 16; off; off >>= 1) {
            float v2 = __shfl_xor_sync(0xffffffffu, v, off);
            int k2 = __shfl_xor_sync(0xffffffffu, kk, off);
            if (v2 > v || (v2 == v && k2 < kk)) { v = v2; kk = k2; }
        }
        if (l == 0) { best[b][i] = v; prevrow[i] = (float)kk; }
        __syncwarp();
    }
    if (l == 0) preds[b] = best[b][lengths[b]];
}

extern "C" void kernel_launch(void* const* d_in, const int* in_sizes, int n_in,
                              void* d_out, int out_size) {
    const float* x    = (const float*)d_in[0];
    const int*   len  = (const int*)  d_in[1];
    const float* Wif  = (const float*)d_in[2];
    const float* Whf  = (const float*)d_in[3];
    const float* bf   = (const float*)d_in[4];
    const float* Wib  = (const float*)d_in[5];
    const float* Whb  = (const float*)d_in[6];
    const float* bbv  = (const float*)d_in[7];
    const float* a1   = (const float*)d_in[8];
    const float* W1   = (const float*)d_in[9];
    const float* b1   = (const float*)d_in[10];
    const float* a2   = (const float*)d_in[11];
    const float* W2   = (const float*)d_in[12];
    const float* b2   = (const float*)d_in[13];
    const float* ac1  = (const float*)d_in[14];
    const float* Wc1  = (const float*)d_in[15];
    const float* bc1  = (const float*)d_in[16];
    const float* ac2  = (const float*)d_in[17];
    const float* Wc2  = (const float*)d_in[18];
    const float* bc2  = (const float*)d_in[19];
    const float* ab1  = (const float*)d_in[20];
    const float* Wb1  = (const float*)d_in[21];
    const float* bb1  = (const float*)d_in[22];
    const float* ab2  = (const float*)d_in[23];
    const float* Wb2  = (const float*)d_in[24];
    const float* bb2  = (const float*)d_in[25];
    float* out = (float*)d_out;

    static int smem_set = 0;
    if (!smem_set) {
        cudaFuncSetAttribute(k_scores, cudaFuncAttributeMaxDynamicSharedMemorySize,
                             SMEM_FLOATS * 4);
        smem_set = 1;
    }

    k_prep<<<2, 256>>>(Whf, Whb);
    k_w1t<<<128, 256>>>(W1);
    k_xwi<<<dim3(SQ, 4), 512>>>(x, Wif, bf, Wib, bbv);
    k_lstm<<<4, 256>>>(Whf, Whb);
    k_cumsum<<<1, 512>>>();
    k_pxde<<<dim3(NP, NBAT), 256>>>(W1, b1, a1);
    k_heads<<<dim3(SQ, NBAT), 256>>>(Wc1, bc1, Wc2, bc2, Wb1, bb1, Wb2, bb2,
                                     ac1, ac2, ab1, ab2,
                                     out + 321602, out + 361602);
    k_scores<<<dim3(NP, NBAT), 256, SMEM_FLOATS * 4>>>(W2, b2, a1, a2, out);
    k_dp<<<1, 64>>>(len, out);
}

// round 7
// speedup vs baseline: 1.1037x; 1.0040x over previous
#include <cuda_runtime.h>

typedef unsigned long long u64;

#define NBAT 2
#define SQ 400
#define IW 80
#define HD 128
#define FD 256
#define NP 401
#define NPAD 416
#define KPD 128

__device__ float g_xWi[4 * SQ * 512];
__device__ float g_xp [NBAT * NP * FD];
__device__ float g_cum[NBAT * NPAD * FD];
__device__ float g_pxd[NBAT * NP * KPD];
__device__ float g_pxe[NBAT * NP * KPD];
__device__ float g_W1T[FD * KPD];
__device__ float g_sT [NBAT * NP * NP];

__device__ __forceinline__ float preluf(float x, float a) { return x >= 0.f ? x : a * x; }
__device__ __forceinline__ float sigf(float x) { return 1.f / (1.f + __expf(-x)); }
__device__ __forceinline__ float tanhfast(float x) {
    float xc = fminf(fmaxf(x, -15.f), 15.f);
    float t = __expf(-2.f * xc);
    return (1.f - t) / (1.f + t);
}
__device__ __forceinline__ void ffma2(u64& c, u64 a, u64 b) {
    asm("fma.rn.f32x2 %0, %1, %2, %0;" : "+l"(c) : "l"(a), "l"(b));
}
__device__ __forceinline__ u64 dupf(float x) {
    u64 r; asm("mov.b64 %0, {%1, %1};" : "=l"(r) : "f"(x)); return r;
}
__device__ __forceinline__ float2 unpk(u64 u) {
    float2 r; asm("mov.b64 {%0, %1}, %2;" : "=f"(r.x), "=f"(r.y) : "l"(u)); return r;
}
__device__ __forceinline__ unsigned smem_u32(const void* p) {
    unsigned a;
    asm("{ .reg .u64 t; cvta.to.shared.u64 t, %1; cvt.u32.u64 %0, t; }" : "=r"(a) : "l"(p));
    return a;
}

// ---- W1c transpose (one-time) ----
__global__ void k_w1t(const float* __restrict__ W1) {
    int idx = blockIdx.x * 256 + threadIdx.x;
    int f = idx >> 7, k = idx & 127;
    g_W1T[idx] = (k < 100) ? W1[k * 768 + f] : 0.f;
}

// ---- xWi = x @ Wi^T + b ----
__global__ void k_xwi(const float* __restrict__ x, const float* __restrict__ Wif,
                      const float* __restrict__ bf, const float* __restrict__ Wib,
                      const float* __restrict__ bbv) {
    int t = blockIdx.x, ch = blockIdx.y, d = ch >> 1, bb = ch & 1;
    const float* Wi = d ? Wib : Wif;
    const float* bi = d ? bbv : bf;
    __shared__ __align__(16) float sx[IW];
    int g = threadIdx.x;
    if (g < IW) sx[g] = x[(bb * SQ + t) * IW + g];
    __syncthreads();
    float acc = bi[g];
    const float4* wr = (const float4*)(Wi + g * IW);
    const float4* xr = (const float4*)sx;
#pragma unroll
    for (int q = 0; q < IW / 4; q++) {
        float4 w = wr[q], xv = xr[q];
        acc += w.x * xv.x + w.y * xv.y + w.z * xv.z + w.w * xv.w;
    }
    g_xWi[(ch * SQ + t) * 512 + g] = acc;
}

// ---- LSTM: one 4-CTA cluster per chain; weights fully register-resident ----
__global__ void __launch_bounds__(256, 1) __cluster_dims__(4, 1, 1)
k_lstm(const float* __restrict__ Whf, const float* __restrict__ Whb) {
    int chain = blockIdx.x >> 2;
    int rank  = blockIdx.x & 3;
    int d = chain >> 1, b = chain & 1;
    const float* Wh = d ? Whb : Whf;
    int t = threadIdx.x;
    int rl = t >> 1;                 // local gate-row 0..127
    int half = t & 1;                // column half
    int gate = rl >> 5, ul = rl & 31;
    int ug = rank * 32 + ul;         // global hidden unit for this row
    int grow = gate * 128 + ug;      // global gate row in Wh

    __shared__ __align__(16) float shbuf[2][HD];
    __shared__ float sg[128];

    // 32 u64 = 64 weight floats per thread (whole matrix in cluster RF)
    u64 w[32];
    {
        const u64* wsrc = (const u64*)(Wh + grow * HD + half * 64);
#pragma unroll
        for (int q = 0; q < 32; q++) w[q] = wsrc[q];
    }
    if (t < HD) shbuf[0][t] = 0.f;
    float cst = 0.f;

    const float* xw = g_xWi + (chain * SQ) * 512;
    float* xpo = g_xp + (b * NP) * FD + d * HD;
    unsigned dsm_base[2];
    dsm_base[0] = smem_u32(&shbuf[0][0]);
    dsm_base[1] = smem_u32(&shbuf[1][0]);

    int tt0 = d ? (SQ - 1) : 0;
    float xwv = xw[tt0 * 512 + grow];

    // make zero-init of shbuf[0] visible cluster-wide before anyone reads it
    asm volatile("barrier.cluster.arrive.aligned;" ::: "memory");
    asm volatile("barrier.cluster.wait.aligned;" ::: "memory");

    for (int s = 0; s < SQ; s++) {
        int tt = d ? (SQ - 1 - s) : s;
        const u64* hv = ((const u64*)shbuf[s & 1]) + half * 32;
        u64 a0 = 0, a1 = 0, a2 = 0, a3 = 0;
#pragma unroll
        for (int q = 0; q < 8; q++) {
            ffma2(a0, hv[4 * q],     w[4 * q]);
            ffma2(a1, hv[4 * q + 1], w[4 * q + 1]);
            ffma2(a2, hv[4 * q + 2], w[4 * q + 2]);
            ffma2(a3, hv[4 * q + 3], w[4 * q + 3]);
        }
        float2 p0 = unpk(a0), p1 = unpk(a1), p2 = unpk(a2), p3 = unpk(a3);
        float sum = ((p0.x + p0.y) + (p1.x + p1.y)) + ((p2.x + p2.y) + (p3.x + p3.y));
        sum += __shfl_xor_sync(0xffffffffu, sum, 1);
        if (half == 0) sg[rl] = sum + xwv;
        if (s + 1 < SQ) {
            int tn = d ? (SQ - 2 - s) : (s + 1);
            xwv = xw[tn * 512 + grow];
        }
        __syncthreads();
        if (t < 32) {
            float iv = sigf(sg[t]);
            float fv = sigf(sg[32 + t]);
            float gv = tanhfast(sg[64 + t]);
            float ov = sigf(sg[96 + t]);
            cst = fv * cst + iv * gv;
            float h = ov * tanhfast(cst);
            int myug = rank * 32 + t;
            xpo[(tt + 1) * FD + myug] = h;
            unsigned dst = dsm_base[(s + 1) & 1] + myug * 4;
#pragma unroll
            for (int r = 0; r < 4; r++) {
                unsigned rem;
                asm("mapa.shared::cluster.u32 %0, %1, %2;" : "=r"(rem) : "r"(dst), "r"(r));
                asm volatile("st.shared::cluster.f32 [%0], %1;" :: "r"(rem), "f"(h) : "memory");
            }
        }
        asm volatile("barrier.cluster.arrive.aligned;" ::: "memory");
        asm volatile("barrier.cluster.wait.aligned;" ::: "memory");
    }
}

// ---- cumsum (+ zero pads) ----
__global__ void k_cumsum() {
    int b = threadIdx.x >> 8, f = threadIdx.x & 255;
    float* xp = g_xp + b * NP * FD + f;
    float* cm = g_cum + b * NPAD * FD + f;
    xp[0] = 0.f; cm[0] = 0.f;
    float a = 0.f;
    for (int n = 1; n < NP; n++) { a += xp[n * FD]; cm[n * FD] = a; }
    for (int n = NP; n < NPAD; n++) cm[n * FD] = 0.f;
}

// ---- pxd / pxe ----
__global__ void k_pxde(const float* __restrict__ W1, const float* __restrict__ b1,
                       const float* __restrict__ a1) {
    int n = blockIdx.x, b = blockIdx.y, t = threadIdx.x;
    __shared__ __align__(16) float sx[FD];
    float A = a1[0];
    sx[t] = preluf(g_xp[(b * NP + n) * FD + t], A);
    __syncthreads();
    int k = t & 127, which = t >> 7;
    float* dst = (which ? g_pxe : g_pxd) + (b * NP + n) * KPD + k;
    if (k >= 100) { *dst = 0.f; return; }
    const float4* wr = (const float4*)(W1 + k * 768 + (which ? 512 : 256));
    const float4* xr = (const float4*)sx;
    float acc = which ? 0.f : b1[k];
#pragma unroll 16
    for (int q = 0; q < 64; q++) {
        float4 w = wr[q], xv = xr[q];
        acc += w.x * xv.x + w.y * xv.y + w.z * xv.z + w.w * xv.w;
    }
    *dst = acc;
}

// ---- big span-scoring kernel ----
#define OFF_V   32768
#define OFF_CI  (32768 + 64 * 210)
#define OFF_PXD (OFF_CI + 256)
#define OFF_W2  (OFF_PXD + 128)
#define SMEM_FLOATS (OFF_W2 + 128)

__global__ void __launch_bounds__(256, 1)
k_scores(const float* __restrict__ W2, const float* __restrict__ b2,
         const float* __restrict__ a1p, const float* __restrict__ a2p,
         float* __restrict__ outp) {
    extern __shared__ __align__(16) float sm[];
    float* sW  = sm;
    float* sV  = sm + OFF_V;
    float* sCI = sm + OFF_CI;
    float* sPD = sm + OFF_PXD;
    float* sW2 = sm + OFF_W2;
    int i = blockIdx.x, b = blockIdx.y, tid = threadIdx.x;
    int w = tid >> 5, l = tid & 31;
    float A1 = a1p[0], A2 = a2p[0], B2 = b2[0];
    for (int idx = tid; idx < 32768; idx += 256) sW[idx] = g_W1T[idx];
    sCI[tid] = g_cum[(b * NPAD + i) * FD + tid];
    if (tid < 128) {
        sPD[tid] = g_pxd[(b * NP + i) * KPD + tid];
        sW2[tid] = (tid < 100) ? W2[tid] : 0.f;
    }
    for (int pass = 0; pass < 2; pass++) {
        int jbase = pass * 208;
        int j0w = jbase + w * 26;
        u64 acc[13][4];
#pragma unroll
        for (int jp = 0; jp < 13; jp++) { acc[jp][0]=0; acc[jp][1]=0; acc[jp][2]=0; acc[jp][3]=0; }
        for (int fc = 0; fc < 4; fc++) {
            __syncthreads();
            for (int idx = tid; idx < 208 * 64; idx += 256) {
                int jl = idx >> 6, fl = idx & 63;
                int f = fc * 64 + fl;
                sV[fl * 210 + jl] = preluf(g_cum[(b * NPAD + jbase + jl) * FD + f] - sCI[f], A1);
            }
            __syncthreads();
            const float* sWf = sW + (fc * 64) * 128;
            for (int f = 0; f < 64; f++) {
                const u64* vr = (const u64*)(sV + f * 210 + w * 26);
                float4 wv = ((const float4*)(sWf + f * 128))[l];
                u64 d0 = dupf(wv.x), d1 = dupf(wv.y), d2 = dupf(wv.z), d3 = dupf(wv.w);
#pragma unroll
                for (int jp = 0; jp < 13; jp++) {
                    u64 v = vr[jp];
                    ffma2(acc[jp][0], v, d0); ffma2(acc[jp][1], v, d1);
                    ffma2(acc[jp][2], v, d2); ffma2(acc[jp][3], v, d3);
                }
            }
        }
#pragma unroll
        for (int jp = 0; jp < 13; jp++) {
            float2 u0 = unpk(acc[jp][0]), u1 = unpk(acc[jp][1]);
            float2 u2 = unpk(acc[jp][2]), u3 = unpk(acc[jp][3]);
#pragma unroll
            for (int half = 0; half < 2; half++) {
                int j = j0w + 2 * jp + half;
                float s = 0.f;
                if (j < NP) {
                    float4 pe = *(const float4*)(g_pxe + (b * NP + j) * KPD + 4 * l);
                    float a0 = half ? u0.y : u0.x, a1v = half ? u1.y : u1.x;
                    float a2v = half ? u2.y : u2.x, a3 = half ? u3.y : u3.x;
                    float h0 = a0 + sPD[4*l]   + pe.x;
                    float h1 = a1v + sPD[4*l+1] + pe.y;
                    float h2 = a2v + sPD[4*l+2] + pe.z;
                    float h3 = a3 + sPD[4*l+3] + pe.w;
                    s = preluf(h0,A2)*sW2[4*l] + preluf(h1,A2)*sW2[4*l+1]
                      + preluf(h2,A2)*sW2[4*l+2] + preluf(h3,A2)*sW2[4*l+3];
                }
#pragma unroll
                for (int off = 16; off; off >>= 1) s += __shfl_xor_sync(0xffffffffu, s, off);
                if (j < NP && l == 0) {
                    float r = s + B2;
                    outp[(b * NP + i) * NP + j] = r;
                    g_sT[(b * NP + j) * NP + i] = r;
                }
            }
        }
    }
}

// ---- cls / bin heads ----
__global__ void k_heads(const float* __restrict__ Wc1, const float* __restrict__ bc1,
                        const float* __restrict__ Wc2, const float* __restrict__ bc2,
                        const float* __restrict__ Wb1, const float* __restrict__ bb1,
                        const float* __restrict__ Wb2, const float* __restrict__ bb2,
                        const float* __restrict__ ac1, const float* __restrict__ ac2,
                        const float* __restrict__ ab1, const float* __restrict__ ab2,
                        float* __restrict__ oc, float* __restrict__ ob) {
    int t = blockIdx.x, b = blockIdx.y, tid = threadIdx.x;
    __shared__ __align__(16) float prc[FD], prb[FD], hc[100], hb[100];
    float x = g_xp[(b * NP + t + 1) * FD + tid];
    prc[tid] = preluf(x, ac1[0]);
    prb[tid] = preluf(x, ab1[0]);
    __syncthreads();
    if (tid < 100) {
        float acc = bc1[tid];
        const float4* wr = (const float4*)(Wc1 + tid * FD);
        const float4* xr = (const float4*)prc;
#pragma unroll 8
        for (int q = 0; q < 64; q++) {
            float4 wv = wr[q], xv = xr[q];
            acc += wv.x*xv.x + wv.y*xv.y + wv.z*xv.z + wv.w*xv.w;
        }
        hc[tid] = preluf(acc, ac2[0]);
    } else if (tid >= 128 && tid < 228) {
        int k = tid - 128;
        float acc = bb1[k];
        const float4* wr = (const float4*)(Wb1 + k * FD);
        const float4* xr = (const float4*)prb;
#pragma unroll 8
        for (int q = 0; q < 64; q++) {
            float4 wv = wr[q], xv = xr[q];
            acc += wv.x*xv.x + wv.y*xv.y + wv.z*xv.z + wv.w*xv.w;
        }
        hb[k] = preluf(acc, ab2[0]);
    }
    __syncthreads();
    if (tid < 50) {
        float acc = bc2[tid];
        for (int q = 0; q < 100; q++) acc += Wc2[tid * 100 + q] * hc[q];
        oc[(b * SQ + t) * 50 + tid] = acc;
    } else if (tid >= 64 && tid < 66) {
        int r = tid - 64;
        float acc = bb2[r];
        for (int q = 0; q < 100; q++) acc += Wb2[r * 100 + q] * hb[q];
        ob[(b * SQ + t) * 2 + r] = acc;
    }
}

// ---- banded Viterbi DP (transposed reads + 1-deep prefetch) ----
__global__ void k_dp(const int* __restrict__ lengths, float* __restrict__ outp) {
    int b = threadIdx.x >> 5, l = threadIdx.x & 31;
    __shared__ float best[NBAT][NP];
    for (int n = l; n < NP; n += 32) best[b][n] = 0.f;
    float* prevrow = outp + 363204 + b * NP;
    float* preds   = outp + 363202;
    if (l == 0) prevrow[0] = 0.f;
    __syncwarp();
    const float* sT = g_sT + b * NP * NP;
    float p0 = sT[1 * NP + l];
    float p1 = sT[1 * NP + (l + 32 > NP - 1 ? NP - 1 : l + 32)];
    for (int i = 1; i < NP; i++) {
        int k0 = i - 50; if (k0 < 0) k0 = 0;
        int cnt = i - k0;
        float c0 = (l < cnt)      ? best[b][k0 + l]      + p0 : -1e30f;
        float c1 = (l + 32 < cnt) ? best[b][k0 + l + 32] + p1 : -1e30f;
        if (i + 1 < NP) {
            int kn = i + 1 - 50; if (kn < 0) kn = 0;
            int i2 = kn + l + 32; if (i2 > NP - 1) i2 = NP - 1;
            p0 = sT[(i + 1) * NP + kn + l];
            p1 = sT[(i + 1) * NP + i2];
        }
        float v = c0; int kk = k0 + l;
        if (c1 > v) { v = c1; kk = k0 + l + 32; }
#pragma unroll
        for (int off = 16; off; off >>= 1) {
            float v2 = __shfl_xor_sync(0xffffffffu, v, off);
            int k2 = __shfl_xor_sync(0xffffffffu, kk, off);
            if (v2 > v || (v2 == v && k2 < kk)) { v = v2; kk = k2; }
        }
        if (l == 0) { best[b][i] = v; prevrow[i] = (float)kk; }
        __syncwarp();
    }
    if (l == 0) preds[b] = best[b][lengths[b]];
}

extern "C" void kernel_launch(void* const* d_in, const int* in_sizes, int n_in,
                              void* d_out, int out_size) {
    const float* x    = (const float*)d_in[0];
    const int*   len  = (const int*)  d_in[1];
    const float* Wif  = (const float*)d_in[2];
    const float* Whf  = (const float*)d_in[3];
    const float* bf   = (const float*)d_in[4];
    const float* Wib  = (const float*)d_in[5];
    const float* Whb  = (const float*)d_in[6];
    const float* bbv  = (const float*)d_in[7];
    const float* a1   = (const float*)d_in[8];
    const float* W1   = (const float*)d_in[9];
    const float* b1   = (const float*)d_in[10];
    const float* a2   = (const float*)d_in[11];
    const float* W2   = (const float*)d_in[12];
    const float* b2   = (const float*)d_in[13];
    const float* ac1  = (const float*)d_in[14];
    const float* Wc1  = (const float*)d_in[15];
    const float* bc1  = (const float*)d_in[16];
    const float* ac2  = (const float*)d_in[17];
    const float* Wc2  = (const float*)d_in[18];
    const float* bc2  = (const float*)d_in[19];
    const float* ab1  = (const float*)d_in[20];
    const float* Wb1  = (const float*)d_in[21];
    const float* bb1  = (const float*)d_in[22];
    const float* ab2  = (const float*)d_in[23];
    const float* Wb2  = (const float*)d_in[24];
    const float* bb2  = (const float*)d_in[25];
    float* out = (float*)d_out;

    static int smem_set = 0;
    if (!smem_set) {
        cudaFuncSetAttribute(k_scores, cudaFuncAttributeMaxDynamicSharedMemorySize,
                             SMEM_FLOATS * 4);
        smem_set = 1;
    }

    k_w1t<<<128, 256>>>(W1);
    k_xwi<<<dim3(SQ, 4), 512>>>(x, Wif, bf, Wib, bbv);
    k_lstm<<<16, 256>>>(Whf, Whb);
    k_cumsum<<<1, 512>>>();
    k_pxde<<<dim3(NP, NBAT), 256>>>(W1, b1, a1);
    k_heads<<<dim3(SQ, NBAT), 256>>>(Wc1, bc1, Wc2, bc2, Wb1, bb1, Wb2, bb2,
                                     ac1, ac2, ab1, ab2,
                                     out + 321602, out + 361602);
    k_scores<<<dim3(NP, NBAT), 256, SMEM_FLOATS * 4>>>(W2, b2, a1, a2, out);
    k_dp<<<1, 64>>>(len, out);
}